// round 8
// baseline (speedup 1.0000x reference)
#include <cuda_runtime.h>
#include <cstdint>

#define B_TOTAL 16384
#define RS 68                // rel row stride (floats); pad -> conflict-free LDS, affine addrs
#define RELTILE (16 * RS)    // 1088 floats per m-tile buffer

// ---- dynamic smem layout (float offsets), ~52.3 KB total ----
#define OFF_WP   0           // float4[1024]: paired B-frags of W1_lower (16 KB)
#define OFF_W2   4096        // float[64]
#define OFF_UEP  4160        // float[8][64]: per-warp uep[j]
#define OFF_REL  4672        // float[8][RELTILE]: per-warp rel buffer (34 KB)
#define SMEM_FLOATS (OFF_REL + 8 * RELTILE)
#define SMEM_BYTES  (SMEM_FLOATS * 4)

__device__ __forceinline__ void cp16(float* s, const float* g) {
    uint32_t sa = (uint32_t)__cvta_generic_to_shared(s);
    asm volatile("cp.async.cg.shared.global [%0], [%1], 16;\n" :: "r"(sa), "l"(g));
}
template <int N>
__device__ __forceinline__ void cp_wait() { asm volatile("cp.async.wait_group %0;\n" :: "n"(N)); }

__device__ __forceinline__ void l2_prefetch(const float* g) {
    asm volatile("prefetch.global.L2 [%0];\n" :: "l"(g));
}

// stage one 16x64 rel m-tile -> buf (row stride RS), per-warp, coalesced 16B chunks
__device__ __forceinline__ void stage_tile(float* buf, const float* __restrict__ src, int lane) {
#pragma unroll
    for (int c = 0; c < 8; c++) {
        int i = lane + c * 32;          // chunk 0..255
        int r = i >> 4, s4 = i & 15;
        cp16(buf + r * RS + s4 * 4, src + r * 64 + s4 * 4);
    }
    asm volatile("cp.async.commit_group;\n");
}

__global__ __launch_bounds__(256, 3) void agg_kernel(
    const float* __restrict__ self_v,
    const float* __restrict__ nv,
    const float* __restrict__ rel,
    const float* __restrict__ ue,
    const float* __restrict__ W1,
    const float* __restrict__ b1,
    const float* __restrict__ w2,
    const float* __restrict__ b2,
    float* __restrict__ out)
{
    extern __shared__ __align__(16) float smem[];
    float4* sWp = reinterpret_cast<float4*>(smem + OFF_WP);
    float*  sW2 = smem + OFF_W2;

    const int tid  = threadIdx.x;
    const int warp = tid >> 5;
    const int lane = tid & 31;
    const int g = lane >> 2;          // groupID
    const int q = lane & 3;           // threadID_in_group

    float* myU = smem + OFF_UEP + warp * 64;   // uep[j]
    float* buf = smem + OFF_REL + warp * RELTILE;

    // ---- one-time W staging (only CTA-wide barrier) ----
    // sWp[(jt*4+kp)*32 + lane] = (b0(ks=2kp), b1(2kp), b0(2kp+1), b1(2kp+1))
    for (int i = tid; i < 1024; i += 256) {
        int l2i = i & 31, jtkp = i >> 5;
        int gg = l2i >> 2, qq = l2i & 3;
        int jt = jtkp >> 2, kp = jtkp & 3;
        int col = 8 * jt + gg;
        float x = __ldg(W1 + (64 + 16 * kp + qq)      * 64 + col);
        float y = __ldg(W1 + (64 + 16 * kp + qq + 4)  * 64 + col);
        float z = __ldg(W1 + (64 + 16 * kp + qq + 8)  * 64 + col);
        float w = __ldg(W1 + (64 + 16 * kp + qq + 12) * 64 + col);
        sWp[i] = make_float4(x, y, z, w);
    }
    if (tid < 64) sW2[tid] = __ldg(w2 + tid);
    __syncthreads();

    const int b = blockIdx.x * 8 + warp;
    const float* relb = rel + (size_t)b * 4096;
    const float* nvb  = nv  + (size_t)b * 4096;
    const float b2v = __ldg(b2);

    // ---- prologue: prefetch m-tile 0; L2-prefetch tile 1 + nv tile 0 ----
    stage_tile(buf, relb, lane);
    l2_prefetch(relb + 1024 + lane * 32);
    l2_prefetch(nvb + lane * 32);

    // ---- uep[j] = b1[j] + ue[b] @ W1_upper[:,j]  (overlaps cp.async; W1 L1-hot) ----
    {
        const float* ub = ue + (size_t)b * 64;
        float uev0 = __ldg(ub + lane);
        float uev1 = __ldg(ub + lane + 32);
        float acc0 = __ldg(b1 + lane);
        float acc1 = __ldg(b1 + lane + 32);
#pragma unroll
        for (int k = 0; k < 64; k++) {
            float uk = __shfl_sync(0xffffffffu, (k < 32) ? uev0 : uev1, k & 31);
            acc0 = fmaf(uk, __ldg(W1 + k * 64 + lane),      acc0);
            acc1 = fmaf(uk, __ldg(W1 + k * 64 + lane + 32), acc1);
        }
        myU[lane]      = acc0;
        myU[lane + 32] = acc1;
    }

    // running softmax numerator (per-lane float4 over d-columns) and denominator
    const int c4 = lane & 15, half = lane >> 4;
    float4 agg = make_float4(0.f, 0.f, 0.f, 0.f);
    float teAcc = 0.f;

    // ---- main: 4 m-tiles of 16 neighbors; MMA + fused aggregation ----
#pragma unroll
    for (int mt = 0; mt < 4; mt++) {
        cp_wait<0>();
        __syncwarp();

        // L2 prefetch for rel tile mt+2 and nv tile mt+1 (1 line per lane)
        if (mt < 2) l2_prefetch(relb + (mt + 2) * 1024 + lane * 32);
        if (mt < 3) l2_prefetch(nvb + (mt + 1) * 1024 + lane * 32);

        // A-frags via conflict-free LDS.32 (bank = (4g+8ks+q) mod 32, bijective)
        uint32_t a[8][4];
#pragma unroll
        for (int ks = 0; ks < 8; ks++) {
            const float* r0 = buf + g * RS + 8 * ks;
            const float* r1 = buf + (g + 8) * RS + 8 * ks;
            a[ks][0] = __float_as_uint(r0[q]);
            a[ks][1] = __float_as_uint(r1[q]);
            a[ks][2] = __float_as_uint(r0[q + 4]);
            a[ks][3] = __float_as_uint(r1[q + 4]);
        }

        // restage this buffer for the next m-tile (async; should hit L2 now)
        if (mt < 3) stage_tile(buf, relb + (mt + 1) * 1024, lane);

        float s0 = 0.f, s1 = 0.f;   // score partials for neighbors mt*16+g, +8
#pragma unroll
        for (int jt = 0; jt < 8; jt++) {
            float c0 = 0.f, c1 = 0.f, c2 = 0.f, c3 = 0.f;
#pragma unroll
            for (int kp = 0; kp < 4; kp++) {
                float4 wv = sWp[(jt * 4 + kp) * 32 + lane];
                asm volatile(
                    "mma.sync.aligned.m16n8k8.row.col.f32.tf32.tf32.f32 "
                    "{%0,%1,%2,%3}, {%4,%5,%6,%7}, {%8,%9}, {%0,%1,%2,%3};\n"
                    : "+f"(c0), "+f"(c1), "+f"(c2), "+f"(c3)
                    : "r"(a[2 * kp][0]), "r"(a[2 * kp][1]), "r"(a[2 * kp][2]), "r"(a[2 * kp][3]),
                      "r"(__float_as_uint(wv.x)), "r"(__float_as_uint(wv.y)));
                asm volatile(
                    "mma.sync.aligned.m16n8k8.row.col.f32.tf32.tf32.f32 "
                    "{%0,%1,%2,%3}, {%4,%5,%6,%7}, {%8,%9}, {%0,%1,%2,%3};\n"
                    : "+f"(c0), "+f"(c1), "+f"(c2), "+f"(c3)
                    : "r"(a[2 * kp + 1][0]), "r"(a[2 * kp + 1][1]), "r"(a[2 * kp + 1][2]), "r"(a[2 * kp + 1][3]),
                      "r"(__float_as_uint(wv.z)), "r"(__float_as_uint(wv.w)));
            }
            // C frag cols j = 8*jt + 2q, +1; uep/w2 pairs via one LDS.64 each
            float2 u01 = *reinterpret_cast<const float2*>(myU + 8 * jt + 2 * q);
            float2 v01 = *reinterpret_cast<const float2*>(sW2 + 8 * jt + 2 * q);
            s0 += fmaxf(c0 + u01.x, 0.f) * v01.x + fmaxf(c1 + u01.y, 0.f) * v01.y;
            s1 += fmaxf(c2 + u01.x, 0.f) * v01.x + fmaxf(c3 + u01.y, 0.f) * v01.y;
        }
        // reduce over 4 q-lanes (j distributed over q) -> all lanes hold full score
        s0 += __shfl_xor_sync(0xffffffffu, s0, 1);
        s0 += __shfl_xor_sync(0xffffffffu, s0, 2);
        s1 += __shfl_xor_sync(0xffffffffu, s1, 1);
        s1 += __shfl_xor_sync(0xffffffffu, s1, 2);

        // e for neighbors n = mt*16+g (e0) and mt*16+g+8 (e1), on every lane
        float e0 = __expf(1.f / (1.f + __expf(-(s0 + b2v))));
        float e1 = __expf(1.f / (1.f + __expf(-(s1 + b2v))));
        teAcc += e0 + e1;   // summed over g-lanes at the end

        // ---- fused aggregation for this tile's 16 neighbors ----
        // lane handles local rows r = 2i + half (i=0..7), columns c4*4..c4*4+3
        const float* nvt = nvb + mt * 1024;
#pragma unroll
        for (int i = 0; i < 8; i++) {
            int r = 2 * i + half;                    // 0..15
            float er = (i < 4)
                ? __shfl_sync(0xffffffffu, e0, 4 * r)          // r in 0..7
                : __shfl_sync(0xffffffffu, e1, 4 * (r - 8));   // r in 8..15
            float4 v = __ldg(reinterpret_cast<const float4*>(nvt + r * 64) + c4);
            agg.x = fmaf(er, v.x, agg.x);
            agg.y = fmaf(er, v.y, agg.y);
            agg.z = fmaf(er, v.z, agg.z);
            agg.w = fmaf(er, v.w, agg.w);
        }
    }

    // softmax denominator (teAcc identical across q-lanes; sum over g-lanes)
    teAcc += __shfl_xor_sync(0xffffffffu, teAcc, 4);
    teAcc += __shfl_xor_sync(0xffffffffu, teAcc, 8);
    teAcc += __shfl_xor_sync(0xffffffffu, teAcc, 16);
    float inv_te = __fdividef(1.f, teAcc);

    // combine the two half-lane row partitions
    agg.x += __shfl_xor_sync(0xffffffffu, agg.x, 16);
    agg.y += __shfl_xor_sync(0xffffffffu, agg.y, 16);
    agg.z += __shfl_xor_sync(0xffffffffu, agg.z, 16);
    agg.w += __shfl_xor_sync(0xffffffffu, agg.w, 16);

    if (lane < 16) {
        reinterpret_cast<float4*>(out + (size_t)b * 128 + 64)[c4] =
            make_float4(agg.x * inv_te, agg.y * inv_te, agg.z * inv_te, agg.w * inv_te);
    } else {
        float4 sv = __ldg(reinterpret_cast<const float4*>(self_v + (size_t)b * 64) + c4);
        reinterpret_cast<float4*>(out + (size_t)b * 128)[c4] = sv;
    }
}

extern "C" void kernel_launch(void* const* d_in, const int* in_sizes, int n_in,
                              void* d_out, int out_size) {
    const float* self_v = (const float*)d_in[0];
    const float* nv     = (const float*)d_in[1];
    const float* rel    = (const float*)d_in[2];
    const float* ue     = (const float*)d_in[3];
    const float* W1     = (const float*)d_in[4];
    const float* b1     = (const float*)d_in[5];
    const float* w2     = (const float*)d_in[6];
    const float* b2     = (const float*)d_in[7];
    float* out = (float*)d_out;

    cudaFuncSetAttribute(agg_kernel, cudaFuncAttributeMaxDynamicSharedMemorySize, SMEM_BYTES);
    agg_kernel<<<B_TOTAL / 8, 256, SMEM_BYTES>>>(self_v, nv, rel, ue, W1, b1, w2, b2, out);
}

// round 9
// speedup vs baseline: 1.2041x; 1.2041x over previous
#include <cuda_runtime.h>
#include <cstdint>

#define B_TOTAL 16384
#define RS 68                // rel row stride (floats); pad -> conflict-free LDS, affine addrs
#define RELTILE (16 * RS)    // 1088 floats per m-tile buffer
#define NCTA 444             // 148 SMs x 3 resident CTAs
#define BSTRIDE (NCTA * 8)   // warp-batch stride = 3552

// ---- dynamic smem layout (float offsets), ~52.3 KB total ----
#define OFF_WP   0           // float2[2048]: B-frags of W1_lower  (16 KB)
#define OFF_W2   4096        // float[64]
#define OFF_UEP  4160        // float[8][64]: per-warp uep[j]
#define OFF_REL  4672        // float[8][RELTILE]: per-warp rel buffer (34 KB)
#define SMEM_FLOATS (OFF_REL + 8 * RELTILE)
#define SMEM_BYTES  (SMEM_FLOATS * 4)

__device__ __forceinline__ void cp16(float* s, const float* g) {
    uint32_t sa = (uint32_t)__cvta_generic_to_shared(s);
    asm volatile("cp.async.cg.shared.global [%0], [%1], 16;\n" :: "r"(sa), "l"(g));
}
template <int N>
__device__ __forceinline__ void cp_wait() { asm volatile("cp.async.wait_group %0;\n" :: "n"(N)); }

// stage one 16x64 rel m-tile -> buf (row stride RS), per-warp, coalesced 16B chunks
__device__ __forceinline__ void stage_tile(float* buf, const float* __restrict__ src, int lane) {
#pragma unroll
    for (int c = 0; c < 8; c++) {
        int i = lane + c * 32;          // chunk 0..255
        int r = i >> 4, s4 = i & 15;
        cp16(buf + r * RS + s4 * 4, src + r * 64 + s4 * 4);
    }
    asm volatile("cp.async.commit_group;\n");
}

__global__ __launch_bounds__(256, 3) void agg_kernel(
    const float* __restrict__ self_v,
    const float* __restrict__ nv,
    const float* __restrict__ rel,
    const float* __restrict__ ue,
    const float* __restrict__ W1,
    const float* __restrict__ b1,
    const float* __restrict__ w2,
    const float* __restrict__ b2,
    float* __restrict__ out)
{
    extern __shared__ __align__(16) float smem[];
    float2* sWp = reinterpret_cast<float2*>(smem + OFF_WP);
    float*  sW2 = smem + OFF_W2;

    const int tid  = threadIdx.x;
    const int warp = tid >> 5;
    const int lane = tid & 31;
    const int g = lane >> 2;          // groupID
    const int q = lane & 3;           // threadID_in_group

    float* myU = smem + OFF_UEP + warp * 64;   // uep[j]
    float* buf = smem + OFF_REL + warp * RELTILE;

    // ---- one-time W staging (only CTA-wide barrier; once per persistent CTA) ----
    for (int i = tid; i < 2048; i += 256) {
        int l2 = i & 31, jtks = i >> 5;
        int gg = l2 >> 2, qq = l2 & 3;
        int jt = jtks >> 3, ks = jtks & 7;
        float bb0 = __ldg(W1 + (64 + 8 * ks + qq)     * 64 + 8 * jt + gg);
        float bb1 = __ldg(W1 + (64 + 8 * ks + qq + 4) * 64 + 8 * jt + gg);
        sWp[i] = make_float2(bb0, bb1);
    }
    if (tid < 64) sW2[tid] = __ldg(w2 + tid);
    __syncthreads();

    const float b2v = __ldg(b2);
    const int c4 = lane & 15, half = lane >> 4;

    int b = blockIdx.x * 8 + warp;
    if (b < B_TOTAL) {
        // prologue: prefetch first batch's m-tile 0
        stage_tile(buf, rel + (size_t)b * 4096, lane);

        for (;;) {
            const float* relb = rel + (size_t)b * 4096;
            const float* nvb  = nv  + (size_t)b * 4096;
            const int nb = b + BSTRIDE;
            const bool has_next = nb < B_TOTAL;

            // ---- uep[j] = b1[j] + ue[b] @ W1_upper[:,j] (overlaps tile-0 cp.async) ----
            {
                const float* ub = ue + (size_t)b * 64;
                float uev0 = __ldg(ub + lane);
                float uev1 = __ldg(ub + lane + 32);
                float acc0 = __ldg(b1 + lane);
                float acc1 = __ldg(b1 + lane + 32);
#pragma unroll
                for (int k = 0; k < 64; k++) {
                    float uk = __shfl_sync(0xffffffffu, (k < 32) ? uev0 : uev1, k & 31);
                    acc0 = fmaf(uk, __ldg(W1 + k * 64 + lane),      acc0);
                    acc1 = fmaf(uk, __ldg(W1 + k * 64 + lane + 32), acc1);
                }
                myU[lane]      = acc0;
                myU[lane + 32] = acc1;
            }

            float4 agg = make_float4(0.f, 0.f, 0.f, 0.f);
            float teAcc = 0.f;

            // ---- 4 m-tiles of 16 neighbors; MMA + fused aggregation ----
#pragma unroll
            for (int mt = 0; mt < 4; mt++) {
                cp_wait<0>();
                __syncwarp();

                // A-frags via conflict-free LDS.32 (bank = (4g+8ks+q) mod 32)
                uint32_t a[8][4];
#pragma unroll
                for (int ks = 0; ks < 8; ks++) {
                    const float* r0 = buf + g * RS + 8 * ks;
                    const float* r1 = buf + (g + 8) * RS + 8 * ks;
                    a[ks][0] = __float_as_uint(r0[q]);
                    a[ks][1] = __float_as_uint(r1[q]);
                    a[ks][2] = __float_as_uint(r0[q + 4]);
                    a[ks][3] = __float_as_uint(r1[q + 4]);
                }

                // restage: next tile, or next batch's tile 0 (pipeline never drains)
                if (mt < 3)           stage_tile(buf, relb + (mt + 1) * 1024, lane);
                else if (has_next)    stage_tile(buf, rel + (size_t)nb * 4096, lane);

                float s0 = 0.f, s1 = 0.f;   // scores for neighbors mt*16+g, +8
#pragma unroll
                for (int jt = 0; jt < 8; jt++) {
                    float c0 = 0.f, c1 = 0.f, c2 = 0.f, c3 = 0.f;
#pragma unroll
                    for (int ks = 0; ks < 8; ks++) {
                        float2 bv = sWp[(jt * 8 + ks) * 32 + lane];
                        asm volatile(
                            "mma.sync.aligned.m16n8k8.row.col.f32.tf32.tf32.f32 "
                            "{%0,%1,%2,%3}, {%4,%5,%6,%7}, {%8,%9}, {%0,%1,%2,%3};\n"
                            : "+f"(c0), "+f"(c1), "+f"(c2), "+f"(c3)
                            : "r"(a[ks][0]), "r"(a[ks][1]), "r"(a[ks][2]), "r"(a[ks][3]),
                              "r"(__float_as_uint(bv.x)), "r"(__float_as_uint(bv.y)));
                    }
                    float u0 = myU[8 * jt + 2 * q], u1 = myU[8 * jt + 2 * q + 1];
                    float v0 = sW2[8 * jt + 2 * q], v1 = sW2[8 * jt + 2 * q + 1];
                    s0 += fmaxf(c0 + u0, 0.f) * v0 + fmaxf(c1 + u1, 0.f) * v1;
                    s1 += fmaxf(c2 + u0, 0.f) * v0 + fmaxf(c3 + u1, 0.f) * v1;
                }
                s0 += __shfl_xor_sync(0xffffffffu, s0, 1);
                s0 += __shfl_xor_sync(0xffffffffu, s0, 2);
                s1 += __shfl_xor_sync(0xffffffffu, s1, 1);
                s1 += __shfl_xor_sync(0xffffffffu, s1, 2);

                float e0 = __expf(1.f / (1.f + __expf(-(s0 + b2v))));
                float e1 = __expf(1.f / (1.f + __expf(-(s1 + b2v))));
                teAcc += e0 + e1;

                // fused aggregation for this tile's 16 neighbors
                const float* nvt = nvb + mt * 1024;
#pragma unroll
                for (int i = 0; i < 8; i++) {
                    int r = 2 * i + half;                    // 0..15
                    float er = (i < 4)
                        ? __shfl_sync(0xffffffffu, e0, 4 * r)
                        : __shfl_sync(0xffffffffu, e1, 4 * (r - 8));
                    float4 v = __ldg(reinterpret_cast<const float4*>(nvt + r * 64) + c4);
                    agg.x = fmaf(er, v.x, agg.x);
                    agg.y = fmaf(er, v.y, agg.y);
                    agg.z = fmaf(er, v.z, agg.z);
                    agg.w = fmaf(er, v.w, agg.w);
                }
            }

            // softmax denominator (teAcc identical across q-lanes; sum over g)
            teAcc += __shfl_xor_sync(0xffffffffu, teAcc, 4);
            teAcc += __shfl_xor_sync(0xffffffffu, teAcc, 8);
            teAcc += __shfl_xor_sync(0xffffffffu, teAcc, 16);
            float inv_te = __fdividef(1.f, teAcc);

            agg.x += __shfl_xor_sync(0xffffffffu, agg.x, 16);
            agg.y += __shfl_xor_sync(0xffffffffu, agg.y, 16);
            agg.z += __shfl_xor_sync(0xffffffffu, agg.z, 16);
            agg.w += __shfl_xor_sync(0xffffffffu, agg.w, 16);

            if (lane < 16) {
                reinterpret_cast<float4*>(out + (size_t)b * 128 + 64)[c4] =
                    make_float4(agg.x * inv_te, agg.y * inv_te,
                                agg.z * inv_te, agg.w * inv_te);
            } else {
                float4 sv = __ldg(reinterpret_cast<const float4*>(self_v + (size_t)b * 64) + c4);
                reinterpret_cast<float4*>(out + (size_t)b * 128)[c4] = sv;
            }

            if (!has_next) break;
            b = nb;
        }
    }
}

extern "C" void kernel_launch(void* const* d_in, const int* in_sizes, int n_in,
                              void* d_out, int out_size) {
    const float* self_v = (const float*)d_in[0];
    const float* nv     = (const float*)d_in[1];
    const float* rel    = (const float*)d_in[2];
    const float* ue     = (const float*)d_in[3];
    const float* W1     = (const float*)d_in[4];
    const float* b1     = (const float*)d_in[5];
    const float* w2     = (const float*)d_in[6];
    const float* b2     = (const float*)d_in[7];
    float* out = (float*)d_out;

    cudaFuncSetAttribute(agg_kernel, cudaFuncAttributeMaxDynamicSharedMemorySize, SMEM_BYTES);
    agg_kernel<<<NCTA, 256, SMEM_BYTES>>>(self_v, nv, rel, ue, W1, b1, w2, b2, out);
}